// round 1
// baseline (speedup 1.0000x reference)
#include <cuda_runtime.h>
#include <math.h>

#define T_DIM 2048
#define D_DIM 2048
#define H_NUM 16
#define DH_DIM 128

// Scratch (allocation-free rule: __device__ globals)
__device__ float g_Q[T_DIM * D_DIM];
__device__ float g_K[T_DIM * D_DIM];
__device__ float g_V[T_DIM * D_DIM];
__device__ float g_Y[T_DIM * D_DIM];

// ---------------------------------------------------------------------------
// C[m][n] = sum_k A[m][k] * B[n][k] + bias[n]   (NT GEMM, M=N=K=2048)
// BM=BN=64, BK=16, 256 threads, 4x4 register micro-tile.
// ---------------------------------------------------------------------------
__global__ __launch_bounds__(256) void gemm_nt_bias(
    const float* __restrict__ A, const float* __restrict__ B,
    const float* __restrict__ bias, float* __restrict__ C) {
  constexpr int BM = 64, BK = 16, K = D_DIM;
  __shared__ __align__(16) float As[BK][BM];
  __shared__ __align__(16) float Bs[BK][BM];
  const int tid = threadIdx.x;
  const int tx = tid & 15, ty = tid >> 4;
  const int m0 = blockIdx.y * BM, n0 = blockIdx.x * BM;
  const int lrow = tid >> 2, lc4 = tid & 3;  // 64 rows x 4 float4-cols loaders

  float acc[4][4] = {};
  const float* Aptr = A + (m0 + lrow) * K + lc4 * 4;
  const float* Bptr = B + (n0 + lrow) * K + lc4 * 4;

  for (int k0 = 0; k0 < K; k0 += BK) {
    float4 a = *(const float4*)(Aptr + k0);
    float4 b = *(const float4*)(Bptr + k0);
    __syncthreads();  // previous iteration's compute done before overwrite
    As[lc4 * 4 + 0][lrow] = a.x; As[lc4 * 4 + 1][lrow] = a.y;
    As[lc4 * 4 + 2][lrow] = a.z; As[lc4 * 4 + 3][lrow] = a.w;
    Bs[lc4 * 4 + 0][lrow] = b.x; Bs[lc4 * 4 + 1][lrow] = b.y;
    Bs[lc4 * 4 + 2][lrow] = b.z; Bs[lc4 * 4 + 3][lrow] = b.w;
    __syncthreads();
#pragma unroll
    for (int kk = 0; kk < BK; kk++) {
      float4 av = *(const float4*)&As[kk][ty * 4];
      float4 bv = *(const float4*)&Bs[kk][tx * 4];
      float a4[4] = {av.x, av.y, av.z, av.w};
      float b4[4] = {bv.x, bv.y, bv.z, bv.w};
#pragma unroll
      for (int i = 0; i < 4; i++)
#pragma unroll
        for (int j = 0; j < 4; j++) acc[i][j] += a4[i] * b4[j];
    }
  }

#pragma unroll
  for (int i = 0; i < 4; i++) {
#pragma unroll
    for (int j = 0; j < 4; j++) {
      C[(m0 + ty * 4 + i) * D_DIM + n0 + tx * 4 + j] =
          acc[i][j] + bias[n0 + tx * 4 + j];
    }
  }
}

// ---------------------------------------------------------------------------
// Flash attention, fp32, causal. One CTA per (head, 64-row Q tile).
// ---------------------------------------------------------------------------
struct AttnSmem {
  float Qt[DH_DIM][64];   // Q transposed (k-major), pre-scaled
  float Kt[DH_DIM][64];   // K transposed (k-major)
  float V[64][DH_DIM];
  float S[64][65];        // scores / probabilities (padded)
  float m[64];
  float l[64];
  float alpha[64];
};

__global__ __launch_bounds__(256, 1) void attention_kernel(
    const float* __restrict__ gQ, const float* __restrict__ gK,
    const float* __restrict__ gV, float* __restrict__ gY) {
  extern __shared__ __align__(16) char smem_raw[];
  AttnSmem& s = *reinterpret_cast<AttnSmem*>(smem_raw);

  const int h = blockIdx.y;
  const int qt = blockIdx.x;
  const int q0 = qt * 64;
  const int tid = threadIdx.x;
  const int tx = tid & 15, ty = tid >> 4;
  const float scale = 0.088388347648318447f;  // 1/sqrt(128)

  // Load Q tile (transposed, pre-scaled)
  for (int idx = tid; idx < 64 * DH_DIM; idx += 256) {
    int r = idx >> 7, k = idx & 127;
    s.Qt[k][r] = gQ[(q0 + r) * D_DIM + h * DH_DIM + k] * scale;
  }
  if (tid < 64) { s.m[tid] = -1e30f; s.l[tid] = 0.f; }

  float o[4][8] = {};  // rows ty*4..+3, cols tx*8..+7 of 64x128 O tile

  for (int jt = 0; jt <= qt; jt++) {
    const int k0 = jt * 64;
    __syncthreads();  // prev PV reads done; Q/m/l init visible on first iter
    for (int idx = tid; idx < 64 * DH_DIM; idx += 256) {
      int r = idx >> 7, k = idx & 127;
      s.Kt[k][r] = gK[(k0 + r) * D_DIM + h * DH_DIM + k];
      s.V[r][k]  = gV[(k0 + r) * D_DIM + h * DH_DIM + k];
    }
    __syncthreads();

    // S = Q K^T (64x64), each thread 4x4
    float sc[4][4] = {};
#pragma unroll 8
    for (int k = 0; k < DH_DIM; k++) {
      float4 qv = *(const float4*)&s.Qt[k][ty * 4];
      float4 kv = *(const float4*)&s.Kt[k][tx * 4];
      float q4[4] = {qv.x, qv.y, qv.z, qv.w};
      float k4[4] = {kv.x, kv.y, kv.z, kv.w};
#pragma unroll
      for (int i = 0; i < 4; i++)
#pragma unroll
        for (int j = 0; j < 4; j++) sc[i][j] += q4[i] * k4[j];
    }

    if (jt == qt) {  // causal mask only on diagonal tile
#pragma unroll
      for (int i = 0; i < 4; i++)
#pragma unroll
        for (int j = 0; j < 4; j++) {
          int qr = ty * 4 + i, kc = tx * 4 + j;
          s.S[qr][kc] = (kc > qr) ? -1e30f : sc[i][j];
        }
    } else {
#pragma unroll
      for (int i = 0; i < 4; i++)
#pragma unroll
        for (int j = 0; j < 4; j++) s.S[ty * 4 + i][tx * 4 + j] = sc[i][j];
    }
    __syncthreads();

    // Online softmax: 4 threads per row, 16 cols each
    {
      const int row = tid >> 2, g4 = tid & 3;
      float mx = -1e30f;
#pragma unroll
      for (int c = 0; c < 16; c++) mx = fmaxf(mx, s.S[row][g4 * 16 + c]);
      mx = fmaxf(mx, __shfl_xor_sync(0xffffffffu, mx, 1));
      mx = fmaxf(mx, __shfl_xor_sync(0xffffffffu, mx, 2));
      const float mold = s.m[row];
      const float mnew = fmaxf(mold, mx);
      float sum = 0.f;
#pragma unroll
      for (int c = 0; c < 16; c++) {
        float p = __expf(s.S[row][g4 * 16 + c] - mnew);
        s.S[row][g4 * 16 + c] = p;
        sum += p;
      }
      sum += __shfl_xor_sync(0xffffffffu, sum, 1);
      sum += __shfl_xor_sync(0xffffffffu, sum, 2);
      if (g4 == 0) {
        float a = __expf(mold - mnew);
        s.m[row] = mnew;
        s.l[row] = s.l[row] * a + sum;
        s.alpha[row] = a;
      }
    }
    __syncthreads();

    // Rescale O and accumulate P @ V
#pragma unroll
    for (int i = 0; i < 4; i++) {
      float a = s.alpha[ty * 4 + i];
#pragma unroll
      for (int j = 0; j < 8; j++) o[i][j] *= a;
    }
#pragma unroll 4
    for (int sv = 0; sv < 64; sv++) {
      float4 v0 = *(const float4*)&s.V[sv][tx * 8];
      float4 v1 = *(const float4*)&s.V[sv][tx * 8 + 4];
#pragma unroll
      for (int i = 0; i < 4; i++) {
        float p = s.S[ty * 4 + i][sv];
        o[i][0] += p * v0.x; o[i][1] += p * v0.y;
        o[i][2] += p * v0.z; o[i][3] += p * v0.w;
        o[i][4] += p * v1.x; o[i][5] += p * v1.y;
        o[i][6] += p * v1.z; o[i][7] += p * v1.w;
      }
    }
  }

#pragma unroll
  for (int i = 0; i < 4; i++) {
    float inv = 1.f / s.l[ty * 4 + i];
#pragma unroll
    for (int j = 0; j < 8; j++)
      gY[(q0 + ty * 4 + i) * D_DIM + h * DH_DIM + tx * 8 + j] = o[i][j] * inv;
  }
}

// ---------------------------------------------------------------------------
extern "C" void kernel_launch(void* const* d_in, const int* in_sizes, int n_in,
                              void* d_out, int out_size) {
  const float* x  = (const float*)d_in[0];
  const float* Wq = (const float*)d_in[1];
  const float* bq = (const float*)d_in[2];
  const float* Wk = (const float*)d_in[3];
  const float* bk = (const float*)d_in[4];
  const float* Wv = (const float*)d_in[5];
  const float* bv = (const float*)d_in[6];
  const float* Wo = (const float*)d_in[7];
  const float* bo = (const float*)d_in[8];
  float* out = (float*)d_out;

  float *Q, *K, *V, *Y;
  cudaGetSymbolAddress((void**)&Q, g_Q);
  cudaGetSymbolAddress((void**)&K, g_K);
  cudaGetSymbolAddress((void**)&V, g_V);
  cudaGetSymbolAddress((void**)&Y, g_Y);

  cudaFuncSetAttribute(attention_kernel,
                       cudaFuncAttributeMaxDynamicSharedMemorySize,
                       (int)sizeof(AttnSmem));

  dim3 gg(D_DIM / 64, T_DIM / 64);
  gemm_nt_bias<<<gg, 256>>>(x, Wq, bq, Q);
  gemm_nt_bias<<<gg, 256>>>(x, Wk, bk, K);
  gemm_nt_bias<<<gg, 256>>>(x, Wv, bv, V);
  attention_kernel<<<dim3(T_DIM / 64, H_NUM), 256, sizeof(AttnSmem)>>>(Q, K, V, Y);
  gemm_nt_bias<<<gg, 256>>>(Y, Wo, bo, out);
}

// round 3
// speedup vs baseline: 1.9151x; 1.9151x over previous
#include <cuda_runtime.h>
#include <cuda_bf16.h>
#include <cstdint>
#include <math.h>

#define T_DIM 2048
#define D_DIM 2048
#define H_NUM 16
#define DH_DIM 128

// ---------------------------------------------------------------------------
// Scratch (allocation-free rule: __device__ globals)
// ---------------------------------------------------------------------------
__device__ float g_Q[T_DIM * D_DIM];
__device__ float g_K[T_DIM * D_DIM];
__device__ float g_V[T_DIM * D_DIM];
__device__ float g_Y[T_DIM * D_DIM];
__device__ __nv_bfloat16 g_ah[T_DIM * D_DIM];
__device__ __nv_bfloat16 g_al[T_DIM * D_DIM];
__device__ __nv_bfloat16 g_bh[T_DIM * D_DIM];
__device__ __nv_bfloat16 g_bl[T_DIM * D_DIM];

// ---------------------------------------------------------------------------
// Plain-PTX helpers (sm_100, no 'a' features): cp.async / ldmatrix / mma.sync
// ---------------------------------------------------------------------------
__device__ __forceinline__ uint32_t smem_u32(const void* p) {
  uint32_t a;
  asm("{ .reg .u64 t; cvta.to.shared.u64 t, %1; cvt.u32.u64 %0, t; }"
      : "=r"(a) : "l"(p));
  return a;
}
#define SW128(off) ((off) ^ (((off) >> 3) & 0x70))

__device__ __forceinline__ void cp16(uint32_t dst, const void* src) {
  asm volatile("cp.async.cg.shared.global [%0], [%1], 16;" :: "r"(dst), "l"(src));
}
__device__ __forceinline__ void cp_commit() {
  asm volatile("cp.async.commit_group;" ::: "memory");
}
template <int N> __device__ __forceinline__ void cp_wait() {
  asm volatile("cp.async.wait_group %0;" :: "n"(N) : "memory");
}
__device__ __forceinline__ void ldsm4(uint32_t* r, uint32_t addr) {
  asm volatile("ldmatrix.sync.aligned.m8n8.x4.shared.b16 {%0,%1,%2,%3}, [%4];"
               : "=r"(r[0]), "=r"(r[1]), "=r"(r[2]), "=r"(r[3]) : "r"(addr));
}
__device__ __forceinline__ void mma16816(float* c, const uint32_t* a,
                                         const uint32_t* b) {
  asm volatile(
      "mma.sync.aligned.m16n8k16.row.col.f32.bf16.bf16.f32 "
      "{%0,%1,%2,%3},{%4,%5,%6,%7},{%8,%9},{%0,%1,%2,%3};"
      : "+f"(c[0]), "+f"(c[1]), "+f"(c[2]), "+f"(c[3])
      : "r"(a[0]), "r"(a[1]), "r"(a[2]), "r"(a[3]), "r"(b[0]), "r"(b[1]));
}

// ---------------------------------------------------------------------------
// fp32 -> (bf16 hi, bf16 lo) split
// ---------------------------------------------------------------------------
__global__ __launch_bounds__(256) void split_bf16(
    const float* __restrict__ src, __nv_bfloat16* __restrict__ hi,
    __nv_bfloat16* __restrict__ lo) {
  int i = blockIdx.x * 256 + threadIdx.x;
  float4 v = ((const float4*)src)[i];
  float f[4] = {v.x, v.y, v.z, v.w};
  __nv_bfloat16 h[4], l[4];
#pragma unroll
  for (int k = 0; k < 4; k++) {
    h[k] = __float2bfloat16_rn(f[k]);
    l[k] = __float2bfloat16_rn(f[k] - __bfloat162float(h[k]));
  }
  ((__nv_bfloat162*)hi)[2 * i]     = __nv_bfloat162(h[0], h[1]);
  ((__nv_bfloat162*)hi)[2 * i + 1] = __nv_bfloat162(h[2], h[3]);
  ((__nv_bfloat162*)lo)[2 * i]     = __nv_bfloat162(l[0], l[1]);
  ((__nv_bfloat162*)lo)[2 * i + 1] = __nv_bfloat162(l[2], l[3]);
}

// ---------------------------------------------------------------------------
// NT GEMM via mma.sync bf16x3: C[m][n] = sum_k A[m,k]*B[n,k] + bias[n]
// BM=256 BN=128 BK=64, 512 threads (4x4 warps, 64x32 warp tile),
// cp.async double buffer, SW128 swizzle. Grid 16x8 = 128 CTAs (1 wave).
// ---------------------------------------------------------------------------
#define BM 256
#define BN 128
#define BK 64
#define STAGE_A (BM * BK * 2)                 // 32KB per A tile
#define STAGE_B (BN * BK * 2)                 // 16KB per B tile
#define SM_AH 0
#define SM_AL STAGE_A
#define SM_BH (2 * STAGE_A)
#define SM_BL (2 * STAGE_A + STAGE_B)
#define STAGE_SZ (2 * STAGE_A + 2 * STAGE_B)  // 96KB
#define GSMEM (2 * STAGE_SZ + 1024)

__global__ __launch_bounds__(512, 1) void gemm_bf16x3(
    const __nv_bfloat16* __restrict__ Ah, const __nv_bfloat16* __restrict__ Al,
    const __nv_bfloat16* __restrict__ Bh, const __nv_bfloat16* __restrict__ Bl,
    const float* __restrict__ bias, float* __restrict__ C) {
  extern __shared__ __align__(16) char sraw[];
  const uint32_t sb = (smem_u32(sraw) + 1023u) & ~1023u;
  const int tid = threadIdx.x;
  const int lane = tid & 31, wid = tid >> 5;
  const int wm = wid & 3, wn = wid >> 2;  // 4 m-warps x 4 n-warps
  const int m0 = blockIdx.y * BM, n0 = blockIdx.x * BN;

  float acc[4][4][4] = {};

  auto load_stage = [&](int chunk, int stg) {
    const uint32_t s0 = sb + stg * STAGE_SZ;
    const int k0 = chunk * BK;
#pragma unroll
    for (int j = 0; j < 4; j++) {
      int lin = tid + j * 512;           // 0..2047
      int r = lin >> 3, c = lin & 7;     // 256 rows x 8 16B-chunks
      uint32_t sw = SW128((uint32_t)(r * 128 + c * 16));
      const long go = (long)(m0 + r) * D_DIM + k0 + c * 8;
      cp16(s0 + SM_AH + sw, Ah + go);
      cp16(s0 + SM_AL + sw, Al + go);
    }
#pragma unroll
    for (int j = 0; j < 2; j++) {
      int lin = tid + j * 512;           // 0..1023
      int r = lin >> 3, c = lin & 7;     // 128 rows
      uint32_t sw = SW128((uint32_t)(r * 128 + c * 16));
      const long go = (long)(n0 + r) * D_DIM + k0 + c * 8;
      cp16(s0 + SM_BH + sw, Bh + go);
      cp16(s0 + SM_BL + sw, Bl + go);
    }
    cp_commit();
  };

  load_stage(0, 0);
  const int NC = D_DIM / BK;  // 32
#pragma unroll 1
  for (int chunk = 0; chunk < NC; chunk++) {
    if (chunk + 1 < NC) {
      load_stage(chunk + 1, (chunk + 1) & 1);
      cp_wait<1>();
    } else {
      cp_wait<0>();
    }
    __syncthreads();
    const uint32_t s0 = sb + (chunk & 1) * STAGE_SZ;

#pragma unroll
    for (int ks = 0; ks < 4; ks++) {
      uint32_t af[4][4];       // A fragments (Ah, later Al)
      uint32_t bh_[4][2], bl_[4][2];
      // A-hi fragments: 4 m16 tiles
#pragma unroll
      for (int mt = 0; mt < 4; mt++) {
        uint32_t off = (uint32_t)((wm * 64 + mt * 16 + (lane & 15)) * 128 +
                                  ks * 32 + (lane >> 4) * 16);
        ldsm4(af[mt], s0 + SM_AH + SW128(off));
      }
      // B-hi / B-lo fragments: 2 n16 tiles -> 4 n8 pieces
#pragma unroll
      for (int nt = 0; nt < 2; nt++) {
        uint32_t off = (uint32_t)(
            (wn * 32 + nt * 16 + (lane & 7) + ((lane >> 4) << 3)) * 128 +
            ks * 32 + ((lane >> 3) & 1) * 16);
        uint32_t r[4];
        ldsm4(r, s0 + SM_BH + SW128(off));
        bh_[2 * nt][0] = r[0]; bh_[2 * nt][1] = r[1];
        bh_[2 * nt + 1][0] = r[2]; bh_[2 * nt + 1][1] = r[3];
        ldsm4(r, s0 + SM_BL + SW128(off));
        bl_[2 * nt][0] = r[0]; bl_[2 * nt][1] = r[1];
        bl_[2 * nt + 1][0] = r[2]; bl_[2 * nt + 1][1] = r[3];
      }
      // Ah*Bh + Ah*Bl
#pragma unroll
      for (int mt = 0; mt < 4; mt++)
#pragma unroll
        for (int np = 0; np < 4; np++) {
          mma16816(acc[mt][np], af[mt], bh_[np]);
          mma16816(acc[mt][np], af[mt], bl_[np]);
        }
      // Al*Bh
#pragma unroll
      for (int mt = 0; mt < 4; mt++) {
        uint32_t off = (uint32_t)((wm * 64 + mt * 16 + (lane & 15)) * 128 +
                                  ks * 32 + (lane >> 4) * 16);
        ldsm4(af[mt], s0 + SM_AL + SW128(off));
      }
#pragma unroll
      for (int mt = 0; mt < 4; mt++)
#pragma unroll
        for (int np = 0; np < 4; np++)
          mma16816(acc[mt][np], af[mt], bh_[np]);
    }
    __syncthreads();
  }

  // Epilogue: c0,c1 -> (row, col..col+1); c2,c3 -> (row+8, ...)
  const int crow = lane >> 2, ccol = (lane & 3) * 2;
#pragma unroll
  for (int np = 0; np < 4; np++) {
    const int col = n0 + wn * 32 + np * 8 + ccol;
    const float2 bb = *(const float2*)(bias + col);
#pragma unroll
    for (int mt = 0; mt < 4; mt++) {
      const int r0 = m0 + wm * 64 + mt * 16 + crow;
      float2 v0 = {acc[mt][np][0] + bb.x, acc[mt][np][1] + bb.y};
      float2 v1 = {acc[mt][np][2] + bb.x, acc[mt][np][3] + bb.y};
      *(float2*)(C + (long)r0 * D_DIM + col) = v0;
      *(float2*)(C + (long)(r0 + 8) * D_DIM + col) = v1;
    }
  }
}

// ---------------------------------------------------------------------------
// Flash attention, fp32, causal (round-1 version, known-good).
// ---------------------------------------------------------------------------
struct AttnSmem {
  float Qt[DH_DIM][64];
  float Kt[DH_DIM][64];
  float V[64][DH_DIM];
  float S[64][65];
  float m[64];
  float l[64];
  float alpha[64];
};

__global__ __launch_bounds__(256, 1) void attention_kernel(
    const float* __restrict__ gQ, const float* __restrict__ gK,
    const float* __restrict__ gV, float* __restrict__ gY) {
  extern __shared__ __align__(16) char smem_raw[];
  AttnSmem& s = *reinterpret_cast<AttnSmem*>(smem_raw);

  const int h = blockIdx.y;
  const int qt = blockIdx.x;
  const int q0 = qt * 64;
  const int tid = threadIdx.x;
  const int tx = tid & 15, ty = tid >> 4;
  const float scale = 0.088388347648318447f;

  for (int idx = tid; idx < 64 * DH_DIM; idx += 256) {
    int r = idx >> 7, k = idx & 127;
    s.Qt[k][r] = gQ[(q0 + r) * D_DIM + h * DH_DIM + k] * scale;
  }
  if (tid < 64) { s.m[tid] = -1e30f; s.l[tid] = 0.f; }

  float o[4][8] = {};

  for (int jt = 0; jt <= qt; jt++) {
    const int k0 = jt * 64;
    __syncthreads();
    for (int idx = tid; idx < 64 * DH_DIM; idx += 256) {
      int r = idx >> 7, k = idx & 127;
      s.Kt[k][r] = gK[(k0 + r) * D_DIM + h * DH_DIM + k];
      s.V[r][k]  = gV[(k0 + r) * D_DIM + h * DH_DIM + k];
    }
    __syncthreads();

    float sc[4][4] = {};
#pragma unroll 8
    for (int k = 0; k < DH_DIM; k++) {
      float4 qv = *(const float4*)&s.Qt[k][ty * 4];
      float4 kv = *(const float4*)&s.Kt[k][tx * 4];
      float q4[4] = {qv.x, qv.y, qv.z, qv.w};
      float k4[4] = {kv.x, kv.y, kv.z, kv.w};
#pragma unroll
      for (int i = 0; i < 4; i++)
#pragma unroll
        for (int j = 0; j < 4; j++) sc[i][j] += q4[i] * k4[j];
    }

    if (jt == qt) {
#pragma unroll
      for (int i = 0; i < 4; i++)
#pragma unroll
        for (int j = 0; j < 4; j++) {
          int qr = ty * 4 + i, kc = tx * 4 + j;
          s.S[qr][kc] = (kc > qr) ? -1e30f : sc[i][j];
        }
    } else {
#pragma unroll
      for (int i = 0; i < 4; i++)
#pragma unroll
        for (int j = 0; j < 4; j++) s.S[ty * 4 + i][tx * 4 + j] = sc[i][j];
    }
    __syncthreads();

    {
      const int row = tid >> 2, g4 = tid & 3;
      float mx = -1e30f;
#pragma unroll
      for (int c = 0; c < 16; c++) mx = fmaxf(mx, s.S[row][g4 * 16 + c]);
      mx = fmaxf(mx, __shfl_xor_sync(0xffffffffu, mx, 1));
      mx = fmaxf(mx, __shfl_xor_sync(0xffffffffu, mx, 2));
      const float mold = s.m[row];
      const float mnew = fmaxf(mold, mx);
      float sum = 0.f;
#pragma unroll
      for (int c = 0; c < 16; c++) {
        float p = __expf(s.S[row][g4 * 16 + c] - mnew);
        s.S[row][g4 * 16 + c] = p;
        sum += p;
      }
      sum += __shfl_xor_sync(0xffffffffu, sum, 1);
      sum += __shfl_xor_sync(0xffffffffu, sum, 2);
      if (g4 == 0) {
        float a = __expf(mold - mnew);
        s.m[row] = mnew;
        s.l[row] = s.l[row] * a + sum;
        s.alpha[row] = a;
      }
    }
    __syncthreads();

#pragma unroll
    for (int i = 0; i < 4; i++) {
      float a = s.alpha[ty * 4 + i];
#pragma unroll
      for (int j = 0; j < 8; j++) o[i][j] *= a;
    }
#pragma unroll 4
    for (int sv = 0; sv < 64; sv++) {
      float4 v0 = *(const float4*)&s.V[sv][tx * 8];
      float4 v1 = *(const float4*)&s.V[sv][tx * 8 + 4];
#pragma unroll
      for (int i = 0; i < 4; i++) {
        float p = s.S[ty * 4 + i][sv];
        o[i][0] += p * v0.x; o[i][1] += p * v0.y;
        o[i][2] += p * v0.z; o[i][3] += p * v0.w;
        o[i][4] += p * v1.x; o[i][5] += p * v1.y;
        o[i][6] += p * v1.z; o[i][7] += p * v1.w;
      }
    }
  }

#pragma unroll
  for (int i = 0; i < 4; i++) {
    float inv = 1.f / s.l[ty * 4 + i];
#pragma unroll
    for (int j = 0; j < 8; j++)
      gY[(q0 + ty * 4 + i) * D_DIM + h * DH_DIM + tx * 8 + j] = o[i][j] * inv;
  }
}

// ---------------------------------------------------------------------------
extern "C" void kernel_launch(void* const* d_in, const int* in_sizes, int n_in,
                              void* d_out, int out_size) {
  const float* x  = (const float*)d_in[0];
  const float* Wq = (const float*)d_in[1];
  const float* bq = (const float*)d_in[2];
  const float* Wk = (const float*)d_in[3];
  const float* bk = (const float*)d_in[4];
  const float* Wv = (const float*)d_in[5];
  const float* bv = (const float*)d_in[6];
  const float* Wo = (const float*)d_in[7];
  const float* bo = (const float*)d_in[8];
  float* out = (float*)d_out;

  float *Q, *K, *V, *Y;
  __nv_bfloat16 *ah, *al, *bh, *bl;
  cudaGetSymbolAddress((void**)&Q, g_Q);
  cudaGetSymbolAddress((void**)&K, g_K);
  cudaGetSymbolAddress((void**)&V, g_V);
  cudaGetSymbolAddress((void**)&Y, g_Y);
  cudaGetSymbolAddress((void**)&ah, g_ah);
  cudaGetSymbolAddress((void**)&al, g_al);
  cudaGetSymbolAddress((void**)&bh, g_bh);
  cudaGetSymbolAddress((void**)&bl, g_bl);

  cudaFuncSetAttribute(attention_kernel,
                       cudaFuncAttributeMaxDynamicSharedMemorySize,
                       (int)sizeof(AttnSmem));
  cudaFuncSetAttribute(gemm_bf16x3,
                       cudaFuncAttributeMaxDynamicSharedMemorySize, GSMEM);

  const int NSPLIT = (T_DIM * D_DIM / 4) / 256;
  dim3 gg(D_DIM / BN, T_DIM / BM);  // 16 x 8

  split_bf16<<<NSPLIT, 256>>>(x, ah, al);
  split_bf16<<<NSPLIT, 256>>>(Wq, bh, bl);
  gemm_bf16x3<<<gg, 512, GSMEM>>>(ah, al, bh, bl, bq, Q);
  split_bf16<<<NSPLIT, 256>>>(Wk, bh, bl);
  gemm_bf16x3<<<gg, 512, GSMEM>>>(ah, al, bh, bl, bk, K);
  split_bf16<<<NSPLIT, 256>>>(Wv, bh, bl);
  gemm_bf16x3<<<gg, 512, GSMEM>>>(ah, al, bh, bl, bv, V);

  attention_kernel<<<dim3(T_DIM / 64, H_NUM), 256, sizeof(AttnSmem)>>>(Q, K, V, Y);

  split_bf16<<<NSPLIT, 256>>>(Y, ah, al);
  split_bf16<<<NSPLIT, 256>>>(Wo, bh, bl);
  gemm_bf16x3<<<gg, 512, GSMEM>>>(ah, al, bh, bl, bo, out);
}

// round 4
// speedup vs baseline: 4.2800x; 2.2349x over previous
#include <cuda_runtime.h>
#include <cuda_bf16.h>
#include <cstdint>
#include <math.h>

#define T_DIM 2048
#define D_DIM 2048
#define H_NUM 16
#define DH_DIM 128

// ---------------------------------------------------------------------------
// Scratch (allocation-free rule: __device__ globals)
// ---------------------------------------------------------------------------
__device__ float g_Q[T_DIM * D_DIM];
__device__ float g_K[T_DIM * D_DIM];
__device__ float g_V[T_DIM * D_DIM];
__device__ float g_Y[T_DIM * D_DIM];
__device__ __nv_bfloat16 g_ah[T_DIM * D_DIM];
__device__ __nv_bfloat16 g_al[T_DIM * D_DIM];
__device__ __nv_bfloat16 g_bh[T_DIM * D_DIM];
__device__ __nv_bfloat16 g_bl[T_DIM * D_DIM];
__device__ __nv_bfloat16 g_qh[T_DIM * D_DIM];
__device__ __nv_bfloat16 g_ql[T_DIM * D_DIM];
__device__ __nv_bfloat16 g_kh[T_DIM * D_DIM];
__device__ __nv_bfloat16 g_kl[T_DIM * D_DIM];
__device__ __nv_bfloat16 g_vth[T_DIM * D_DIM];  // [H][dh][T]
__device__ __nv_bfloat16 g_vtl[T_DIM * D_DIM];

// ---------------------------------------------------------------------------
// Plain-PTX helpers (sm_100-safe): cp.async / ldmatrix / mma.sync
// ---------------------------------------------------------------------------
__device__ __forceinline__ uint32_t smem_u32(const void* p) {
  uint32_t a;
  asm("{ .reg .u64 t; cvta.to.shared.u64 t, %1; cvt.u32.u64 %0, t; }"
      : "=r"(a) : "l"(p));
  return a;
}
#define SW128(off) ((off) ^ (((off) >> 3) & 0x70))

__device__ __forceinline__ void cp16(uint32_t dst, const void* src) {
  asm volatile("cp.async.cg.shared.global [%0], [%1], 16;" :: "r"(dst), "l"(src));
}
__device__ __forceinline__ void cp_commit() {
  asm volatile("cp.async.commit_group;" ::: "memory");
}
template <int N> __device__ __forceinline__ void cp_wait() {
  asm volatile("cp.async.wait_group %0;" :: "n"(N) : "memory");
}
__device__ __forceinline__ void ldsm4(uint32_t* r, uint32_t addr) {
  asm volatile("ldmatrix.sync.aligned.m8n8.x4.shared.b16 {%0,%1,%2,%3}, [%4];"
               : "=r"(r[0]), "=r"(r[1]), "=r"(r[2]), "=r"(r[3]) : "r"(addr));
}
__device__ __forceinline__ void mma16816(float* c, const uint32_t* a,
                                         const uint32_t* b) {
  asm volatile(
      "mma.sync.aligned.m16n8k16.row.col.f32.bf16.bf16.f32 "
      "{%0,%1,%2,%3},{%4,%5,%6,%7},{%8,%9},{%0,%1,%2,%3};"
      : "+f"(c[0]), "+f"(c[1]), "+f"(c[2]), "+f"(c[3])
      : "r"(a[0]), "r"(a[1]), "r"(a[2]), "r"(a[3]), "r"(b[0]), "r"(b[1]));
}
__device__ __forceinline__ uint32_t pack_bf16(float lo, float hi) {
  __nv_bfloat162 t(__float2bfloat16_rn(lo), __float2bfloat16_rn(hi));
  return *(uint32_t*)&t;
}

// ---------------------------------------------------------------------------
// fp32 -> (bf16 hi, bf16 lo) split, optional scale
// ---------------------------------------------------------------------------
__global__ __launch_bounds__(256) void split_bf16(
    const float* __restrict__ src, __nv_bfloat16* __restrict__ hi,
    __nv_bfloat16* __restrict__ lo, float scale) {
  int i = blockIdx.x * 256 + threadIdx.x;
  float4 v = ((const float4*)src)[i];
  float f[4] = {v.x * scale, v.y * scale, v.z * scale, v.w * scale};
  __nv_bfloat16 h[4], l[4];
#pragma unroll
  for (int k = 0; k < 4; k++) {
    h[k] = __float2bfloat16_rn(f[k]);
    l[k] = __float2bfloat16_rn(f[k] - __bfloat162float(h[k]));
  }
  ((__nv_bfloat162*)hi)[2 * i]     = __nv_bfloat162(h[0], h[1]);
  ((__nv_bfloat162*)hi)[2 * i + 1] = __nv_bfloat162(h[2], h[3]);
  ((__nv_bfloat162*)lo)[2 * i]     = __nv_bfloat162(l[0], l[1]);
  ((__nv_bfloat162*)lo)[2 * i + 1] = __nv_bfloat162(l[2], l[3]);
}

// ---------------------------------------------------------------------------
// V transpose-split: V[T,D] fp32 -> Vt[h][dh][T] bf16 hi/lo
// ---------------------------------------------------------------------------
__global__ __launch_bounds__(256) void transpose_split_v(
    const float* __restrict__ V, __nv_bfloat16* __restrict__ vth,
    __nv_bfloat16* __restrict__ vtl) {
  __shared__ float tile[32][33];
  const int t0 = blockIdx.x * 32, d0 = blockIdx.y * 32;
  const int c = threadIdx.x & 31, rb = threadIdx.x >> 5;
#pragma unroll
  for (int k = 0; k < 4; k++) {
    int r = rb + k * 8;
    tile[r][c] = V[(long)(t0 + r) * D_DIM + d0 + c];
  }
  __syncthreads();
  const int h = d0 >> 7, dl = d0 & 127;
#pragma unroll
  for (int k = 0; k < 4; k++) {
    int r = rb + k * 8;
    float v = tile[c][r];  // V[t0+c][d0+r]
    __nv_bfloat16 hv = __float2bfloat16_rn(v);
    __nv_bfloat16 lv = __float2bfloat16_rn(v - __bfloat162float(hv));
    long o = (long)h * DH_DIM * T_DIM + (long)(dl + r) * T_DIM + t0 + c;
    vth[o] = hv;
    vtl[o] = lv;
  }
}

// ---------------------------------------------------------------------------
// NT GEMM via mma.sync bf16x3 (round-3, known-good)
// ---------------------------------------------------------------------------
#define BM 256
#define BN 128
#define BK 64
#define STAGE_A (BM * BK * 2)
#define STAGE_B (BN * BK * 2)
#define SM_AH 0
#define SM_AL STAGE_A
#define SM_BH (2 * STAGE_A)
#define SM_BL (2 * STAGE_A + STAGE_B)
#define STAGE_SZ (2 * STAGE_A + 2 * STAGE_B)
#define GSMEM (2 * STAGE_SZ + 1024)

__global__ __launch_bounds__(512, 1) void gemm_bf16x3(
    const __nv_bfloat16* __restrict__ Ah, const __nv_bfloat16* __restrict__ Al,
    const __nv_bfloat16* __restrict__ Bh, const __nv_bfloat16* __restrict__ Bl,
    const float* __restrict__ bias, float* __restrict__ C) {
  extern __shared__ __align__(16) char sraw[];
  const uint32_t sb = (smem_u32(sraw) + 1023u) & ~1023u;
  const int tid = threadIdx.x;
  const int lane = tid & 31, wid = tid >> 5;
  const int wm = wid & 3, wn = wid >> 2;
  const int m0 = blockIdx.y * BM, n0 = blockIdx.x * BN;

  float acc[4][4][4] = {};

  auto load_stage = [&](int chunk, int stg) {
    const uint32_t s0 = sb + stg * STAGE_SZ;
    const int k0 = chunk * BK;
#pragma unroll
    for (int j = 0; j < 4; j++) {
      int lin = tid + j * 512;
      int r = lin >> 3, c = lin & 7;
      uint32_t sw = SW128((uint32_t)(r * 128 + c * 16));
      const long go = (long)(m0 + r) * D_DIM + k0 + c * 8;
      cp16(s0 + SM_AH + sw, Ah + go);
      cp16(s0 + SM_AL + sw, Al + go);
    }
#pragma unroll
    for (int j = 0; j < 2; j++) {
      int lin = tid + j * 512;
      int r = lin >> 3, c = lin & 7;
      uint32_t sw = SW128((uint32_t)(r * 128 + c * 16));
      const long go = (long)(n0 + r) * D_DIM + k0 + c * 8;
      cp16(s0 + SM_BH + sw, Bh + go);
      cp16(s0 + SM_BL + sw, Bl + go);
    }
    cp_commit();
  };

  load_stage(0, 0);
  const int NC = D_DIM / BK;
#pragma unroll 1
  for (int chunk = 0; chunk < NC; chunk++) {
    if (chunk + 1 < NC) {
      load_stage(chunk + 1, (chunk + 1) & 1);
      cp_wait<1>();
    } else {
      cp_wait<0>();
    }
    __syncthreads();
    const uint32_t s0 = sb + (chunk & 1) * STAGE_SZ;

#pragma unroll
    for (int ks = 0; ks < 4; ks++) {
      uint32_t af[4][4];
      uint32_t bh_[4][2], bl_[4][2];
#pragma unroll
      for (int mt = 0; mt < 4; mt++) {
        uint32_t off = (uint32_t)((wm * 64 + mt * 16 + (lane & 15)) * 128 +
                                  ks * 32 + (lane >> 4) * 16);
        ldsm4(af[mt], s0 + SM_AH + SW128(off));
      }
#pragma unroll
      for (int nt = 0; nt < 2; nt++) {
        uint32_t off = (uint32_t)(
            (wn * 32 + nt * 16 + (lane & 7) + ((lane >> 4) << 3)) * 128 +
            ks * 32 + ((lane >> 3) & 1) * 16);
        uint32_t r[4];
        ldsm4(r, s0 + SM_BH + SW128(off));
        bh_[2 * nt][0] = r[0]; bh_[2 * nt][1] = r[1];
        bh_[2 * nt + 1][0] = r[2]; bh_[2 * nt + 1][1] = r[3];
        ldsm4(r, s0 + SM_BL + SW128(off));
        bl_[2 * nt][0] = r[0]; bl_[2 * nt][1] = r[1];
        bl_[2 * nt + 1][0] = r[2]; bl_[2 * nt + 1][1] = r[3];
      }
#pragma unroll
      for (int mt = 0; mt < 4; mt++)
#pragma unroll
        for (int np = 0; np < 4; np++) {
          mma16816(acc[mt][np], af[mt], bh_[np]);
          mma16816(acc[mt][np], af[mt], bl_[np]);
        }
#pragma unroll
      for (int mt = 0; mt < 4; mt++) {
        uint32_t off = (uint32_t)((wm * 64 + mt * 16 + (lane & 15)) * 128 +
                                  ks * 32 + (lane >> 4) * 16);
        ldsm4(af[mt], s0 + SM_AL + SW128(off));
      }
#pragma unroll
      for (int mt = 0; mt < 4; mt++)
#pragma unroll
        for (int np = 0; np < 4; np++)
          mma16816(acc[mt][np], af[mt], bh_[np]);
    }
    __syncthreads();
  }

  const int crow = lane >> 2, ccol = (lane & 3) * 2;
#pragma unroll
  for (int np = 0; np < 4; np++) {
    const int col = n0 + wn * 32 + np * 8 + ccol;
    const float2 bb = *(const float2*)(bias + col);
#pragma unroll
    for (int mt = 0; mt < 4; mt++) {
      const int r0 = m0 + wm * 64 + mt * 16 + crow;
      float2 v0 = {acc[mt][np][0] + bb.x, acc[mt][np][1] + bb.y};
      float2 v1 = {acc[mt][np][2] + bb.x, acc[mt][np][3] + bb.y};
      *(float2*)(C + (long)r0 * D_DIM + col) = v0;
      *(float2*)(C + (long)(r0 + 8) * D_DIM + col) = v1;
    }
  }
}

// ---------------------------------------------------------------------------
// Tensor-core flash attention, bf16x3 for S and PV. causal.
// CTA: (head, 128-row Q tile). 8 warps x 16 rows. KV step = 64.
// ---------------------------------------------------------------------------
#define AQH 0
#define AQL 32768
#define ASTG 65536
#define ASTG_SZ 65536
#define AKH 0
#define AKL 16384
#define AVH 32768
#define AVL 49152
#define ASMEM (ASTG + 2 * ASTG_SZ + 1024)

__global__ __launch_bounds__(256, 1) void attention_mma(
    const __nv_bfloat16* __restrict__ Qh, const __nv_bfloat16* __restrict__ Ql,
    const __nv_bfloat16* __restrict__ Kh, const __nv_bfloat16* __restrict__ Kl,
    const __nv_bfloat16* __restrict__ Vth, const __nv_bfloat16* __restrict__ Vtl,
    float* __restrict__ Y) {
  extern __shared__ __align__(16) char sraw[];
  const uint32_t sb = (smem_u32(sraw) + 1023u) & ~1023u;
  const int tid = threadIdx.x;
  const int lane = tid & 31, wq = tid >> 5;
  const int h = blockIdx.y;
  const int qt = gridDim.x - 1 - blockIdx.x;  // heavy tiles first
  const int q0 = qt * 128;
  const int steps = 2 * qt + 2;

  // Load Q (hi/lo), [2 halves][128 rows][128B], SW128
#pragma unroll
  for (int j = 0; j < 8; j++) {
    int lin = tid + j * 256;
    int r = lin >> 4, c8 = lin & 15;
    uint32_t dst = (uint32_t)((c8 >> 3) * 16384 +
                              SW128(r * 128 + (c8 & 7) * 16));
    long go = (long)(q0 + r) * D_DIM + h * DH_DIM + c8 * 8;
    cp16(sb + AQH + dst, Qh + go);
    cp16(sb + AQL + dst, Ql + go);
  }
  cp_commit();

  auto load_stage = [&](int j, int stg) {
    const uint32_t s0 = sb + ASTG + stg * ASTG_SZ;
    const int k0 = j * 64;
#pragma unroll
    for (int i = 0; i < 4; i++) {             // K: 64 rows x 16 chunks
      int lin = tid + i * 256;
      int r = lin >> 4, c8 = lin & 15;
      uint32_t dst = (uint32_t)((c8 >> 3) * 8192 +
                                SW128(r * 128 + (c8 & 7) * 16));
      long go = (long)(k0 + r) * D_DIM + h * DH_DIM + c8 * 8;
      cp16(s0 + AKH + dst, Kh + go);
      cp16(s0 + AKL + dst, Kl + go);
    }
#pragma unroll
    for (int i = 0; i < 4; i++) {             // Vt: 128 rows x 8 chunks
      int lin = tid + i * 256;
      int d = lin >> 3, c8 = lin & 7;
      uint32_t dst = SW128((uint32_t)(d * 128 + c8 * 16));
      long go = (long)h * DH_DIM * T_DIM + (long)d * T_DIM + k0 + c8 * 8;
      cp16(s0 + AVH + dst, Vth + go);
      cp16(s0 + AVL + dst, Vtl + go);
    }
    cp_commit();
  };

  load_stage(0, 0);

  float o[16][4] = {};
  float m0 = -1e30f, m1 = -1e30f, l0 = 0.f, l1 = 0.f;
  const int row0 = q0 + wq * 16 + (lane >> 2);
  const int row1 = row0 + 8;

#pragma unroll 1
  for (int j = 0; j < steps; j++) {
    if (j + 1 < steps) {
      load_stage(j + 1, (j + 1) & 1);
      cp_wait<1>();
    } else {
      cp_wait<0>();
    }
    __syncthreads();
    const uint32_t s0 = sb + ASTG + (j & 1) * ASTG_SZ;
    const int k0 = j * 64;

    // ---- S = Q K^T (bf16x3), per-warp 16x64 tile ----
    float sf[8][4] = {};
#pragma unroll
    for (int ks = 0; ks < 8; ks++) {
      uint32_t aqh_[4], aql_[4];
      uint32_t aoff = (uint32_t)((ks >> 2) * 16384 +
                                 SW128((wq * 16 + (lane & 15)) * 128 +
                                       (ks & 3) * 32 + (lane >> 4) * 16));
      ldsm4(aqh_, sb + AQH + aoff);
      ldsm4(aql_, sb + AQL + aoff);
      uint32_t bkh[8][2], bkl[8][2];
#pragma unroll
      for (int nt = 0; nt < 4; nt++) {
        uint32_t boff = (uint32_t)((ks >> 2) * 8192 +
            SW128((nt * 16 + (lane & 7) + ((lane >> 4) << 3)) * 128 +
                  (ks & 3) * 32 + ((lane >> 3) & 1) * 16));
        uint32_t r[4];
        ldsm4(r, s0 + AKH + boff);
        bkh[2 * nt][0] = r[0]; bkh[2 * nt][1] = r[1];
        bkh[2 * nt + 1][0] = r[2]; bkh[2 * nt + 1][1] = r[3];
        ldsm4(r, s0 + AKL + boff);
        bkl[2 * nt][0] = r[0]; bkl[2 * nt][1] = r[1];
        bkl[2 * nt + 1][0] = r[2]; bkl[2 * nt + 1][1] = r[3];
      }
#pragma unroll
      for (int nt = 0; nt < 8; nt++) {
        mma16816(sf[nt], aqh_, bkh[nt]);
        mma16816(sf[nt], aqh_, bkl[nt]);
        mma16816(sf[nt], aql_, bkh[nt]);
      }
    }

    // ---- causal mask (last two steps only) ----
    if (j >= 2 * qt) {
#pragma unroll
      for (int nt = 0; nt < 8; nt++) {
        int col = k0 + nt * 8 + ((lane & 3) << 1);
        if (col > row0) sf[nt][0] = -1e30f;
        if (col + 1 > row0) sf[nt][1] = -1e30f;
        if (col > row1) sf[nt][2] = -1e30f;
        if (col + 1 > row1) sf[nt][3] = -1e30f;
      }
    }

    // ---- online softmax ----
    float mx0 = -1e30f, mx1 = -1e30f;
#pragma unroll
    for (int nt = 0; nt < 8; nt++) {
      mx0 = fmaxf(mx0, fmaxf(sf[nt][0], sf[nt][1]));
      mx1 = fmaxf(mx1, fmaxf(sf[nt][2], sf[nt][3]));
    }
    mx0 = fmaxf(mx0, __shfl_xor_sync(0xffffffffu, mx0, 1));
    mx0 = fmaxf(mx0, __shfl_xor_sync(0xffffffffu, mx0, 2));
    mx1 = fmaxf(mx1, __shfl_xor_sync(0xffffffffu, mx1, 1));
    mx1 = fmaxf(mx1, __shfl_xor_sync(0xffffffffu, mx1, 2));
    const float mn0 = fmaxf(m0, mx0), mn1 = fmaxf(m1, mx1);
    const float al0 = __expf(m0 - mn0), al1 = __expf(m1 - mn1);
    float sum0 = 0.f, sum1 = 0.f;
#pragma unroll
    for (int nt = 0; nt < 8; nt++) {
      sf[nt][0] = __expf(sf[nt][0] - mn0); sum0 += sf[nt][0];
      sf[nt][1] = __expf(sf[nt][1] - mn0); sum0 += sf[nt][1];
      sf[nt][2] = __expf(sf[nt][2] - mn1); sum1 += sf[nt][2];
      sf[nt][3] = __expf(sf[nt][3] - mn1); sum1 += sf[nt][3];
    }
    sum0 += __shfl_xor_sync(0xffffffffu, sum0, 1);
    sum0 += __shfl_xor_sync(0xffffffffu, sum0, 2);
    sum1 += __shfl_xor_sync(0xffffffffu, sum1, 1);
    sum1 += __shfl_xor_sync(0xffffffffu, sum1, 2);
    l0 = l0 * al0 + sum0; m0 = mn0;
    l1 = l1 * al1 + sum1; m1 = mn1;
#pragma unroll
    for (int n8 = 0; n8 < 16; n8++) {
      o[n8][0] *= al0; o[n8][1] *= al0;
      o[n8][2] *= al1; o[n8][3] *= al1;
    }

    // ---- O += P V (bf16x3): P packed from S registers ----
#pragma unroll
    for (int kt = 0; kt < 4; kt++) {
      uint32_t aph[4], apl[4];
#pragma unroll
      for (int half = 0; half < 2; half++) {
        const float* p = sf[2 * kt + half];
        float h0 = __bfloat162float(__float2bfloat16_rn(p[0]));
        float h1 = __bfloat162float(__float2bfloat16_rn(p[1]));
        float h2 = __bfloat162float(__float2bfloat16_rn(p[2]));
        float h3 = __bfloat162float(__float2bfloat16_rn(p[3]));
        aph[2 * half + 0] = pack_bf16(h0, h1);
        aph[2 * half + 1] = pack_bf16(h2, h3);
        apl[2 * half + 0] = pack_bf16(p[0] - h0, p[1] - h1);
        apl[2 * half + 1] = pack_bf16(p[2] - h2, p[3] - h3);
      }
#pragma unroll
      for (int nt = 0; nt < 8; nt++) {
        uint32_t voff = SW128((uint32_t)(
            (nt * 16 + (lane & 7) + ((lane >> 4) << 3)) * 128 +
            kt * 32 + ((lane >> 3) & 1) * 16));
        uint32_t vh[4], vl[4];
        ldsm4(vh, s0 + AVH + voff);
        ldsm4(vl, s0 + AVL + voff);
        uint32_t vh_lo[2] = {vh[0], vh[1]}, vh_hi[2] = {vh[2], vh[3]};
        uint32_t vl_lo[2] = {vl[0], vl[1]}, vl_hi[2] = {vl[2], vl[3]};
        mma16816(o[2 * nt], aph, vh_lo);
        mma16816(o[2 * nt], aph, vl_lo);
        mma16816(o[2 * nt], apl, vh_lo);
        mma16816(o[2 * nt + 1], aph, vh_hi);
        mma16816(o[2 * nt + 1], aph, vl_hi);
        mma16816(o[2 * nt + 1], apl, vh_hi);
      }
    }
    __syncthreads();
  }

  // ---- epilogue ----
  const float inv0 = 1.f / l0, inv1 = 1.f / l1;
  const int ccol = (lane & 3) * 2;
#pragma unroll
  for (int n8 = 0; n8 < 16; n8++) {
    const int col = h * DH_DIM + n8 * 8 + ccol;
    float2 v0 = {o[n8][0] * inv0, o[n8][1] * inv0};
    float2 v1 = {o[n8][2] * inv1, o[n8][3] * inv1};
    *(float2*)(Y + (long)row0 * D_DIM + col) = v0;
    *(float2*)(Y + (long)row1 * D_DIM + col) = v1;
  }
}

// ---------------------------------------------------------------------------
extern "C" void kernel_launch(void* const* d_in, const int* in_sizes, int n_in,
                              void* d_out, int out_size) {
  const float* x  = (const float*)d_in[0];
  const float* Wq = (const float*)d_in[1];
  const float* bq = (const float*)d_in[2];
  const float* Wk = (const float*)d_in[3];
  const float* bk = (const float*)d_in[4];
  const float* Wv = (const float*)d_in[5];
  const float* bv = (const float*)d_in[6];
  const float* Wo = (const float*)d_in[7];
  const float* bo = (const float*)d_in[8];
  float* out = (float*)d_out;

  float *Q, *K, *V, *Y;
  __nv_bfloat16 *ah, *al, *bh, *bl, *qh, *ql, *kh, *kl, *vth, *vtl;
  cudaGetSymbolAddress((void**)&Q, g_Q);
  cudaGetSymbolAddress((void**)&K, g_K);
  cudaGetSymbolAddress((void**)&V, g_V);
  cudaGetSymbolAddress((void**)&Y, g_Y);
  cudaGetSymbolAddress((void**)&ah, g_ah);
  cudaGetSymbolAddress((void**)&al, g_al);
  cudaGetSymbolAddress((void**)&bh, g_bh);
  cudaGetSymbolAddress((void**)&bl, g_bl);
  cudaGetSymbolAddress((void**)&qh, g_qh);
  cudaGetSymbolAddress((void**)&ql, g_ql);
  cudaGetSymbolAddress((void**)&kh, g_kh);
  cudaGetSymbolAddress((void**)&kl, g_kl);
  cudaGetSymbolAddress((void**)&vth, g_vth);
  cudaGetSymbolAddress((void**)&vtl, g_vtl);

  cudaFuncSetAttribute(gemm_bf16x3,
                       cudaFuncAttributeMaxDynamicSharedMemorySize, GSMEM);
  cudaFuncSetAttribute(attention_mma,
                       cudaFuncAttributeMaxDynamicSharedMemorySize, ASMEM);

  const int NSPLIT = (T_DIM * D_DIM / 4) / 256;
  dim3 gg(D_DIM / BN, T_DIM / BM);
  const float qscale = 0.088388347648318447f;  // 1/sqrt(128)

  split_bf16<<<NSPLIT, 256>>>(x, ah, al, 1.f);
  split_bf16<<<NSPLIT, 256>>>(Wq, bh, bl, 1.f);
  gemm_bf16x3<<<gg, 512, GSMEM>>>(ah, al, bh, bl, bq, Q);
  split_bf16<<<NSPLIT, 256>>>(Wk, bh, bl, 1.f);
  gemm_bf16x3<<<gg, 512, GSMEM>>>(ah, al, bh, bl, bk, K);
  split_bf16<<<NSPLIT, 256>>>(Wv, bh, bl, 1.f);
  gemm_bf16x3<<<gg, 512, GSMEM>>>(ah, al, bh, bl, bv, V);

  split_bf16<<<NSPLIT, 256>>>(Q, qh, ql, qscale);
  split_bf16<<<NSPLIT, 256>>>(K, kh, kl, 1.f);
  transpose_split_v<<<dim3(T_DIM / 32, D_DIM / 32), 256>>>(V, vth, vtl);

  attention_mma<<<dim3(T_DIM / 128, H_NUM), 256, ASMEM>>>(qh, ql, kh, kl, vth,
                                                          vtl, Y);

  split_bf16<<<NSPLIT, 256>>>(Y, ah, al, 1.f);
  split_bf16<<<NSPLIT, 256>>>(Wo, bh, bl, 1.f);
  gemm_bf16x3<<<gg, 512, GSMEM>>>(ah, al, bh, bl, bo, out);
}

// round 6
// speedup vs baseline: 4.7794x; 1.1167x over previous
#include <cuda_runtime.h>
#include <cuda_bf16.h>
#include <cstdint>
#include <math.h>

#define T_DIM 2048
#define D_DIM 2048
#define H_NUM 16
#define DH_DIM 128

// ---------------------------------------------------------------------------
// Scratch (allocation-free rule: __device__ globals)
// ---------------------------------------------------------------------------
__device__ float g_V[T_DIM * D_DIM];
__device__ __nv_bfloat16 g_ah[T_DIM * D_DIM];   // x split, later Y split
__device__ __nv_bfloat16 g_al[T_DIM * D_DIM];
__device__ __nv_bfloat16 g_qh[T_DIM * D_DIM];
__device__ __nv_bfloat16 g_ql[T_DIM * D_DIM];
__device__ __nv_bfloat16 g_kh[T_DIM * D_DIM];
__device__ __nv_bfloat16 g_kl[T_DIM * D_DIM];
__device__ __nv_bfloat16 g_vth[T_DIM * D_DIM];  // [H][dh][T]
__device__ __nv_bfloat16 g_vtl[T_DIM * D_DIM];
__device__ __nv_bfloat16 g_wqh[T_DIM * D_DIM];
__device__ __nv_bfloat16 g_wql[T_DIM * D_DIM];
__device__ __nv_bfloat16 g_wkh[T_DIM * D_DIM];
__device__ __nv_bfloat16 g_wkl[T_DIM * D_DIM];
__device__ __nv_bfloat16 g_wvh[T_DIM * D_DIM];
__device__ __nv_bfloat16 g_wvl[T_DIM * D_DIM];
__device__ __nv_bfloat16 g_woh[T_DIM * D_DIM];
__device__ __nv_bfloat16 g_wol[T_DIM * D_DIM];

// ---------------------------------------------------------------------------
// Plain-PTX helpers (sm_100-safe)
// ---------------------------------------------------------------------------
__device__ __forceinline__ uint32_t smem_u32(const void* p) {
  uint32_t a;
  asm("{ .reg .u64 t; cvta.to.shared.u64 t, %1; cvt.u32.u64 %0, t; }"
      : "=r"(a) : "l"(p));
  return a;
}
#define SW128(off) ((off) ^ (((off) >> 3) & 0x70))

__device__ __forceinline__ void cp16(uint32_t dst, const void* src) {
  asm volatile("cp.async.cg.shared.global [%0], [%1], 16;" :: "r"(dst), "l"(src));
}
__device__ __forceinline__ void cp_commit() {
  asm volatile("cp.async.commit_group;" ::: "memory");
}
template <int N> __device__ __forceinline__ void cp_wait() {
  asm volatile("cp.async.wait_group %0;" :: "n"(N) : "memory");
}
__device__ __forceinline__ void ldsm4(uint32_t* r, uint32_t addr) {
  asm volatile("ldmatrix.sync.aligned.m8n8.x4.shared.b16 {%0,%1,%2,%3}, [%4];"
               : "=r"(r[0]), "=r"(r[1]), "=r"(r[2]), "=r"(r[3]) : "r"(addr));
}
// NOTE: non-volatile — pure register function, lets ptxas schedule freely.
__device__ __forceinline__ void mma16816(float* c, const uint32_t* a,
                                         const uint32_t* b) {
  asm("mma.sync.aligned.m16n8k16.row.col.f32.bf16.bf16.f32 "
      "{%0,%1,%2,%3},{%4,%5,%6,%7},{%8,%9},{%0,%1,%2,%3};"
      : "+f"(c[0]), "+f"(c[1]), "+f"(c[2]), "+f"(c[3])
      : "r"(a[0]), "r"(a[1]), "r"(a[2]), "r"(a[3]), "r"(b[0]), "r"(b[1]));
}
__device__ __forceinline__ uint32_t pack_bf16(float lo, float hi) {
  __nv_bfloat162 t(__float2bfloat16_rn(lo), __float2bfloat16_rn(hi));
  return *(uint32_t*)&t;
}

// ---------------------------------------------------------------------------
// One-shot split of all 5 fp32 inputs -> bf16 hi/lo pairs  (grid.z selects)
// ---------------------------------------------------------------------------
__global__ __launch_bounds__(256) void split_all(
    const float* __restrict__ x, const float* __restrict__ wq,
    const float* __restrict__ wk, const float* __restrict__ wv,
    const float* __restrict__ wo, __nv_bfloat16* __restrict__ xh,
    __nv_bfloat16* __restrict__ xl, __nv_bfloat16* __restrict__ qh,
    __nv_bfloat16* __restrict__ ql, __nv_bfloat16* __restrict__ kh,
    __nv_bfloat16* __restrict__ kl, __nv_bfloat16* __restrict__ vh,
    __nv_bfloat16* __restrict__ vl, __nv_bfloat16* __restrict__ oh,
    __nv_bfloat16* __restrict__ ol) {
  const int z = blockIdx.z;
  const float* src = (z == 0) ? x : (z == 1) ? wq : (z == 2) ? wk
                     : (z == 3) ? wv : wo;
  __nv_bfloat16* hi = (z == 0) ? xh : (z == 1) ? qh : (z == 2) ? kh
                      : (z == 3) ? vh : oh;
  __nv_bfloat16* lo = (z == 0) ? xl : (z == 1) ? ql : (z == 2) ? kl
                      : (z == 3) ? vl : ol;
  int i = blockIdx.x * 256 + threadIdx.x;
  float4 v = ((const float4*)src)[i];
  float f[4] = {v.x, v.y, v.z, v.w};
  __nv_bfloat16 h[4], l[4];
#pragma unroll
  for (int k = 0; k < 4; k++) {
    h[k] = __float2bfloat16_rn(f[k]);
    l[k] = __float2bfloat16_rn(f[k] - __bfloat162float(h[k]));
  }
  ((__nv_bfloat162*)hi)[2 * i]     = __nv_bfloat162(h[0], h[1]);
  ((__nv_bfloat162*)hi)[2 * i + 1] = __nv_bfloat162(h[2], h[3]);
  ((__nv_bfloat162*)lo)[2 * i]     = __nv_bfloat162(l[0], l[1]);
  ((__nv_bfloat162*)lo)[2 * i + 1] = __nv_bfloat162(l[2], l[3]);
}

// ---------------------------------------------------------------------------
// V transpose-split: V[T,D] fp32 -> Vt[h][dh][T] bf16 hi/lo
// ---------------------------------------------------------------------------
__global__ __launch_bounds__(256) void transpose_split_v(
    const float* __restrict__ V, __nv_bfloat16* __restrict__ vth,
    __nv_bfloat16* __restrict__ vtl) {
  __shared__ float tile[32][33];
  const int t0 = blockIdx.x * 32, d0 = blockIdx.y * 32;
  const int c = threadIdx.x & 31, rb = threadIdx.x >> 5;
#pragma unroll
  for (int k = 0; k < 4; k++) {
    int r = rb + k * 8;
    tile[r][c] = V[(long)(t0 + r) * D_DIM + d0 + c];
  }
  __syncthreads();
  const int h = d0 >> 7, dl = d0 & 127;
#pragma unroll
  for (int k = 0; k < 4; k++) {
    int r = rb + k * 8;
    float v = tile[c][r];
    __nv_bfloat16 hv = __float2bfloat16_rn(v);
    __nv_bfloat16 lv = __float2bfloat16_rn(v - __bfloat162float(hv));
    long o = (long)h * DH_DIM * T_DIM + (long)(dl + r) * T_DIM + t0 + c;
    vth[o] = hv;
    vtl[o] = lv;
  }
}

// ---------------------------------------------------------------------------
// NT GEMM bf16x3, dependency-distance-16 mma ordering.
// split_out=1: write (C+bias)*oscale split into Chi/Clo instead of fp32 C.
// ---------------------------------------------------------------------------
#define BM 256
#define BN 128
#define BK 64
#define STAGE_A (BM * BK * 2)
#define STAGE_B (BN * BK * 2)
#define SM_AH 0
#define SM_AL STAGE_A
#define SM_BH (2 * STAGE_A)
#define SM_BL (2 * STAGE_A + STAGE_B)
#define STAGE_SZ (2 * STAGE_A + 2 * STAGE_B)
#define GSMEM (2 * STAGE_SZ + 1024)

__global__ __launch_bounds__(512, 1) void gemm_bf16x3(
    const __nv_bfloat16* __restrict__ Ah, const __nv_bfloat16* __restrict__ Al,
    const __nv_bfloat16* __restrict__ Bh, const __nv_bfloat16* __restrict__ Bl,
    const float* __restrict__ bias, float* __restrict__ C,
    __nv_bfloat16* __restrict__ Chi, __nv_bfloat16* __restrict__ Clo,
    float oscale, int split_out) {
  extern __shared__ __align__(16) char sraw[];
  const uint32_t sb = (smem_u32(sraw) + 1023u) & ~1023u;
  const int tid = threadIdx.x;
  const int lane = tid & 31, wid = tid >> 5;
  const int wm = wid & 3, wn = wid >> 2;
  const int m0 = blockIdx.y * BM, n0 = blockIdx.x * BN;

  float acc[4][4][4] = {};

  auto load_stage = [&](int chunk, int stg) {
    const uint32_t s0 = sb + stg * STAGE_SZ;
    const int k0 = chunk * BK;
#pragma unroll
    for (int j = 0; j < 4; j++) {
      int lin = tid + j * 512;
      int r = lin >> 3, c = lin & 7;
      uint32_t sw = SW128((uint32_t)(r * 128 + c * 16));
      const long go = (long)(m0 + r) * D_DIM + k0 + c * 8;
      cp16(s0 + SM_AH + sw, Ah + go);
      cp16(s0 + SM_AL + sw, Al + go);
    }
#pragma unroll
    for (int j = 0; j < 2; j++) {
      int lin = tid + j * 512;
      int r = lin >> 3, c = lin & 7;
      uint32_t sw = SW128((uint32_t)(r * 128 + c * 16));
      const long go = (long)(n0 + r) * D_DIM + k0 + c * 8;
      cp16(s0 + SM_BH + sw, Bh + go);
      cp16(s0 + SM_BL + sw, Bl + go);
    }
    cp_commit();
  };

  load_stage(0, 0);
  const int NC = D_DIM / BK;
#pragma unroll 1
  for (int chunk = 0; chunk < NC; chunk++) {
    if (chunk + 1 < NC) {
      load_stage(chunk + 1, (chunk + 1) & 1);
      cp_wait<1>();
    } else {
      cp_wait<0>();
    }
    __syncthreads();
    const uint32_t s0 = sb + (chunk & 1) * STAGE_SZ;

#pragma unroll
    for (int ks = 0; ks < 4; ks++) {
      uint32_t afh[4][4], afl[4][4];
      uint32_t bh_[4][2], bl_[4][2];
#pragma unroll
      for (int mt = 0; mt < 4; mt++) {
        uint32_t off = (uint32_t)((wm * 64 + mt * 16 + (lane & 15)) * 128 +
                                  ks * 32 + (lane >> 4) * 16);
        ldsm4(afh[mt], s0 + SM_AH + SW128(off));
      }
#pragma unroll
      for (int nt = 0; nt < 2; nt++) {
        uint32_t off = (uint32_t)(
            (wn * 32 + nt * 16 + (lane & 7) + ((lane >> 4) << 3)) * 128 +
            ks * 32 + ((lane >> 3) & 1) * 16);
        uint32_t r[4];
        ldsm4(r, s0 + SM_BH + SW128(off));
        bh_[2 * nt][0] = r[0]; bh_[2 * nt][1] = r[1];
        bh_[2 * nt + 1][0] = r[2]; bh_[2 * nt + 1][1] = r[3];
        ldsm4(r, s0 + SM_BL + SW128(off));
        bl_[2 * nt][0] = r[0]; bl_[2 * nt][1] = r[1];
        bl_[2 * nt + 1][0] = r[2]; bl_[2 * nt + 1][1] = r[3];
      }
#pragma unroll
      for (int mt = 0; mt < 4; mt++) {
        uint32_t off = (uint32_t)((wm * 64 + mt * 16 + (lane & 15)) * 128 +
                                  ks * 32 + (lane >> 4) * 16);
        ldsm4(afl[mt], s0 + SM_AL + SW128(off));
      }
      // Pass 1: Ah*Bh — 16 independent accumulators
#pragma unroll
      for (int mt = 0; mt < 4; mt++)
#pragma unroll
        for (int np = 0; np < 4; np++) mma16816(acc[mt][np], afh[mt], bh_[np]);
      // Pass 2: Ah*Bl
#pragma unroll
      for (int mt = 0; mt < 4; mt++)
#pragma unroll
        for (int np = 0; np < 4; np++) mma16816(acc[mt][np], afh[mt], bl_[np]);
      // Pass 3: Al*Bh
#pragma unroll
      for (int mt = 0; mt < 4; mt++)
#pragma unroll
        for (int np = 0; np < 4; np++) mma16816(acc[mt][np], afl[mt], bh_[np]);
    }
    __syncthreads();
  }

  const int crow = lane >> 2, ccol = (lane & 3) * 2;
  if (split_out) {
#pragma unroll
    for (int np = 0; np < 4; np++) {
      const int col = n0 + wn * 32 + np * 8 + ccol;
      const float2 bb = *(const float2*)(bias + col);
#pragma unroll
      for (int mt = 0; mt < 4; mt++) {
        const int r0 = m0 + wm * 64 + mt * 16 + crow;
        float v0 = (acc[mt][np][0] + bb.x) * oscale;
        float v1 = (acc[mt][np][1] + bb.y) * oscale;
        float v2 = (acc[mt][np][2] + bb.x) * oscale;
        float v3 = (acc[mt][np][3] + bb.y) * oscale;
        float h0 = __bfloat162float(__float2bfloat16_rn(v0));
        float h1 = __bfloat162float(__float2bfloat16_rn(v1));
        float h2 = __bfloat162float(__float2bfloat16_rn(v2));
        float h3 = __bfloat162float(__float2bfloat16_rn(v3));
        *(uint32_t*)(Chi + (long)r0 * D_DIM + col) = pack_bf16(v0, v1);
        *(uint32_t*)(Clo + (long)r0 * D_DIM + col) = pack_bf16(v0 - h0, v1 - h1);
        *(uint32_t*)(Chi + (long)(r0 + 8) * D_DIM + col) = pack_bf16(v2, v3);
        *(uint32_t*)(Clo + (long)(r0 + 8) * D_DIM + col) = pack_bf16(v2 - h2, v3 - h3);
      }
    }
  } else {
#pragma unroll
    for (int np = 0; np < 4; np++) {
      const int col = n0 + wn * 32 + np * 8 + ccol;
      const float2 bb = *(const float2*)(bias + col);
#pragma unroll
      for (int mt = 0; mt < 4; mt++) {
        const int r0 = m0 + wm * 64 + mt * 16 + crow;
        float2 v0 = {acc[mt][np][0] + bb.x, acc[mt][np][1] + bb.y};
        float2 v1 = {acc[mt][np][2] + bb.x, acc[mt][np][3] + bb.y};
        *(float2*)(C + (long)r0 * D_DIM + col) = v0;
        *(float2*)(C + (long)(r0 + 8) * D_DIM + col) = v1;
      }
    }
  }
}

// ---------------------------------------------------------------------------
// Tensor-core flash attention, bf16x3, causal, paired Q-tiles for balance.
// CTA handles Q tiles {bx, 15-bx} (exactly 34 KV steps total). 8 warps.
// Output written as bf16 hi/lo split (feeds the final GEMM directly).
// ---------------------------------------------------------------------------
#define AQH 0
#define AQL 32768
#define ASTG 65536
#define ASTG_SZ 65536
#define AKH 0
#define AKL 16384
#define AVH 32768
#define AVL 49152
#define ASMEM (ASTG + 2 * ASTG_SZ + 1024)

__global__ __launch_bounds__(256, 1) void attention_mma(
    const __nv_bfloat16* __restrict__ Qh, const __nv_bfloat16* __restrict__ Ql,
    const __nv_bfloat16* __restrict__ Kh, const __nv_bfloat16* __restrict__ Kl,
    const __nv_bfloat16* __restrict__ Vth, const __nv_bfloat16* __restrict__ Vtl,
    __nv_bfloat16* __restrict__ Yh, __nv_bfloat16* __restrict__ Yl) {
  extern __shared__ __align__(16) char sraw[];
  const uint32_t sb = (smem_u32(sraw) + 1023u) & ~1023u;
  const int tid = threadIdx.x;
  const int lane = tid & 31, wq = tid >> 5;
  const int h = blockIdx.y;

  auto load_stage = [&](int j, int stg) {
    const uint32_t s0 = sb + ASTG + stg * ASTG_SZ;
    const int k0 = j * 64;
#pragma unroll
    for (int i = 0; i < 4; i++) {
      int lin = tid + i * 256;
      int r = lin >> 4, c8 = lin & 15;
      uint32_t dst = (uint32_t)((c8 >> 3) * 8192 +
                                SW128(r * 128 + (c8 & 7) * 16));
      long go = (long)(k0 + r) * D_DIM + h * DH_DIM + c8 * 8;
      cp16(s0 + AKH + dst, Kh + go);
      cp16(s0 + AKL + dst, Kl + go);
    }
#pragma unroll
    for (int i = 0; i < 4; i++) {
      int lin = tid + i * 256;
      int d = lin >> 3, c8 = lin & 7;
      uint32_t dst = SW128((uint32_t)(d * 128 + c8 * 16));
      long go = (long)h * DH_DIM * T_DIM + (long)d * T_DIM + k0 + c8 * 8;
      cp16(s0 + AVH + dst, Vth + go);
      cp16(s0 + AVL + dst, Vtl + go);
    }
    cp_commit();
  };

#pragma unroll 1
  for (int pass = 0; pass < 2; pass++) {
    const int qt = pass ? (T_DIM / 128 - 1 - (int)blockIdx.x) : (int)blockIdx.x;
    const int q0 = qt * 128;
    const int steps = 2 * qt + 2;
    __syncthreads();  // Q buffer reuse across passes

    // Load Q hi/lo
#pragma unroll
    for (int j = 0; j < 8; j++) {
      int lin = tid + j * 256;
      int r = lin >> 4, c8 = lin & 15;
      uint32_t dst = (uint32_t)((c8 >> 3) * 16384 +
                                SW128(r * 128 + (c8 & 7) * 16));
      long go = (long)(q0 + r) * D_DIM + h * DH_DIM + c8 * 8;
      cp16(sb + AQH + dst, Qh + go);
      cp16(sb + AQL + dst, Ql + go);
    }
    cp_commit();
    load_stage(0, 0);

    float o[16][4] = {};
    float m0 = -1e30f, m1 = -1e30f, l0 = 0.f, l1 = 0.f;
    const int row0 = q0 + wq * 16 + (lane >> 2);
    const int row1 = row0 + 8;

#pragma unroll 1
    for (int j = 0; j < steps; j++) {
      if (j + 1 < steps) {
        load_stage(j + 1, (j + 1) & 1);
        cp_wait<1>();
      } else {
        cp_wait<0>();
      }
      __syncthreads();
      const uint32_t s0 = sb + ASTG + (j & 1) * ASTG_SZ;
      const int k0 = j * 64;

      // ---- S = Q K^T, 3 passes of 8 independent accumulators ----
      float sf[8][4] = {};
#pragma unroll
      for (int ks = 0; ks < 8; ks++) {
        uint32_t aqh_[4], aql_[4];
        uint32_t aoff = (uint32_t)((ks >> 2) * 16384 +
                                   SW128((wq * 16 + (lane & 15)) * 128 +
                                         (ks & 3) * 32 + (lane >> 4) * 16));
        ldsm4(aqh_, sb + AQH + aoff);
        ldsm4(aql_, sb + AQL + aoff);
        uint32_t bkh[8][2], bkl[8][2];
#pragma unroll
        for (int nt = 0; nt < 4; nt++) {
          uint32_t boff = (uint32_t)((ks >> 2) * 8192 +
              SW128((nt * 16 + (lane & 7) + ((lane >> 4) << 3)) * 128 +
                    (ks & 3) * 32 + ((lane >> 3) & 1) * 16));
          uint32_t r[4];
          ldsm4(r, s0 + AKH + boff);
          bkh[2 * nt][0] = r[0]; bkh[2 * nt][1] = r[1];
          bkh[2 * nt + 1][0] = r[2]; bkh[2 * nt + 1][1] = r[3];
          ldsm4(r, s0 + AKL + boff);
          bkl[2 * nt][0] = r[0]; bkl[2 * nt][1] = r[1];
          bkl[2 * nt + 1][0] = r[2]; bkl[2 * nt + 1][1] = r[3];
        }
#pragma unroll
        for (int nt = 0; nt < 8; nt++) mma16816(sf[nt], aqh_, bkh[nt]);
#pragma unroll
        for (int nt = 0; nt < 8; nt++) mma16816(sf[nt], aqh_, bkl[nt]);
#pragma unroll
        for (int nt = 0; nt < 8; nt++) mma16816(sf[nt], aql_, bkh[nt]);
      }

      // ---- causal mask ----
      if (j >= 2 * qt) {
#pragma unroll
        for (int nt = 0; nt < 8; nt++) {
          int col = k0 + nt * 8 + ((lane & 3) << 1);
          if (col > row0) sf[nt][0] = -1e30f;
          if (col + 1 > row0) sf[nt][1] = -1e30f;
          if (col > row1) sf[nt][2] = -1e30f;
          if (col + 1 > row1) sf[nt][3] = -1e30f;
        }
      }

      // ---- online softmax ----
      float mx0 = -1e30f, mx1 = -1e30f;
#pragma unroll
      for (int nt = 0; nt < 8; nt++) {
        mx0 = fmaxf(mx0, fmaxf(sf[nt][0], sf[nt][1]));
        mx1 = fmaxf(mx1, fmaxf(sf[nt][2], sf[nt][3]));
      }
      mx0 = fmaxf(mx0, __shfl_xor_sync(0xffffffffu, mx0, 1));
      mx0 = fmaxf(mx0, __shfl_xor_sync(0xffffffffu, mx0, 2));
      mx1 = fmaxf(mx1, __shfl_xor_sync(0xffffffffu, mx1, 1));
      mx1 = fmaxf(mx1, __shfl_xor_sync(0xffffffffu, mx1, 2));
      const float mn0 = fmaxf(m0, mx0), mn1 = fmaxf(m1, mx1);
      const float al0 = __expf(m0 - mn0), al1 = __expf(m1 - mn1);
      float sum0 = 0.f, sum1 = 0.f;
#pragma unroll
      for (int nt = 0; nt < 8; nt++) {
        sf[nt][0] = __expf(sf[nt][0] - mn0); sum0 += sf[nt][0];
        sf[nt][1] = __expf(sf[nt][1] - mn0); sum0 += sf[nt][1];
        sf[nt][2] = __expf(sf[nt][2] - mn1); sum1 += sf[nt][2];
        sf[nt][3] = __expf(sf[nt][3] - mn1); sum1 += sf[nt][3];
      }
      sum0 += __shfl_xor_sync(0xffffffffu, sum0, 1);
      sum0 += __shfl_xor_sync(0xffffffffu, sum0, 2);
      sum1 += __shfl_xor_sync(0xffffffffu, sum1, 1);
      sum1 += __shfl_xor_sync(0xffffffffu, sum1, 2);
      l0 = l0 * al0 + sum0; m0 = mn0;
      l1 = l1 * al1 + sum1; m1 = mn1;
#pragma unroll
      for (int n8 = 0; n8 < 16; n8++) {
        o[n8][0] *= al0; o[n8][1] *= al0;
        o[n8][2] *= al1; o[n8][3] *= al1;
      }

      // ---- O += P V, nt-pairs for dependency distance 4 ----
#pragma unroll
      for (int kt = 0; kt < 4; kt++) {
        uint32_t aph[4], apl[4];
#pragma unroll
        for (int half = 0; half < 2; half++) {
          const float* p = sf[2 * kt + half];
          float h0 = __bfloat162float(__float2bfloat16_rn(p[0]));
          float h1 = __bfloat162float(__float2bfloat16_rn(p[1]));
          float h2 = __bfloat162float(__float2bfloat16_rn(p[2]));
          float h3 = __bfloat162float(__float2bfloat16_rn(p[3]));
          aph[2 * half + 0] = pack_bf16(h0, h1);
          aph[2 * half + 1] = pack_bf16(h2, h3);
          apl[2 * half + 0] = pack_bf16(p[0] - h0, p[1] - h1);
          apl[2 * half + 1] = pack_bf16(p[2] - h2, p[3] - h3);
        }
#pragma unroll
        for (int nt2 = 0; nt2 < 8; nt2 += 2) {
          uint32_t vh0[4], vl0[4], vh1[4], vl1[4];
          uint32_t voff0 = SW128((uint32_t)(
              (nt2 * 16 + (lane & 7) + ((lane >> 4) << 3)) * 128 +
              kt * 32 + ((lane >> 3) & 1) * 16));
          uint32_t voff1 = SW128((uint32_t)(
              ((nt2 + 1) * 16 + (lane & 7) + ((lane >> 4) << 3)) * 128 +
              kt * 32 + ((lane >> 3) & 1) * 16));
          ldsm4(vh0, s0 + AVH + voff0);
          ldsm4(vl0, s0 + AVL + voff0);
          ldsm4(vh1, s0 + AVH + voff1);
          ldsm4(vl1, s0 + AVL + voff1);
          uint32_t vh0_lo[2] = {vh0[0], vh0[1]}, vh0_hi[2] = {vh0[2], vh0[3]};
          uint32_t vl0_lo[2] = {vl0[0], vl0[1]}, vl0_hi[2] = {vl0[2], vl0[3]};
          uint32_t vh1_lo[2] = {vh1[0], vh1[1]}, vh1_hi[2] = {vh1[2], vh1[3]};
          uint32_t vl1_lo[2] = {vl1[0], vl1[1]}, vl1_hi[2] = {vl1[2], vl1[3]};
          mma16816(o[2 * nt2], aph, vh0_lo);
          mma16816(o[2 * nt2 + 1], aph, vh0_hi);
          mma16816(o[2 * nt2 + 2], aph, vh1_lo);
          mma16816(o[2 * nt2 + 3], aph, vh1_hi);
          mma16816(o[2 * nt2], aph, vl0_lo);
          mma16816(o[2 * nt2 + 1], aph, vl0_hi);
          mma16816(o[2 * nt2 + 2], aph, vl1_lo);
          mma16816(o[2 * nt2 + 3], aph, vl1_hi);
          mma16816(o[2 * nt2], apl, vh0_lo);
          mma16816(o[2 * nt2 + 1], apl, vh0_hi);
          mma16816(o[2 * nt2 + 2], apl, vh1_lo);
          mma16816(o[2 * nt2 + 3], apl, vh1_hi);
        }
      }
      __syncthreads();
    }

    // ---- epilogue: write Y split (hi/lo bf16) ----
    const float inv0 = 1.f / l0, inv1 = 1.f / l1;
    const int ccol = (lane & 3) * 2;
#pragma unroll
    for (int n8 = 0; n8 < 16; n8++) {
      const int col = h * DH_DIM + n8 * 8 + ccol;
      float v0 = o[n8][0] * inv0, v1 = o[n8][1] * inv0;
      float v2 = o[n8][2] * inv1, v3 = o[n8][3] * inv1;
      float h0 = __bfloat162float(__float2bfloat16_rn(v0));
      float h1 = __bfloat162float(__float2bfloat16_rn(v1));
      float h2 = __bfloat162float(__float2bfloat16_rn(v2));
      float h3 = __bfloat162float(__float2bfloat16_rn(v3));
      *(uint32_t*)(Yh + (long)row0 * D_DIM + col) = pack_bf16(v0, v1);
      *(uint32_t*)(Yl + (long)row0 * D_DIM + col) = pack_bf16(v0 - h0, v1 - h1);
      *(uint32_t*)(Yh + (long)row1 * D_DIM + col) = pack_bf16(v2, v3);
      *(uint32_t*)(Yl + (long)row1 * D_DIM + col) = pack_bf16(v2 - h2, v3 - h3);
    }
  }
}

// ---------------------------------------------------------------------------
extern "C" void kernel_launch(void* const* d_in, const int* in_sizes, int n_in,
                              void* d_out, int out_size) {
  const float* x  = (const float*)d_in[0];
  const float* Wq = (const float*)d_in[1];
  const float* bq = (const float*)d_in[2];
  const float* Wk = (const float*)d_in[3];
  const float* bk = (const float*)d_in[4];
  const float* Wv = (const float*)d_in[5];
  const float* bv = (const float*)d_in[6];
  const float* Wo = (const float*)d_in[7];
  const float* bo = (const float*)d_in[8];
  float* out = (float*)d_out;

  float* V;
  __nv_bfloat16 *ah, *al, *qh, *ql, *kh, *kl, *vth, *vtl;
  __nv_bfloat16 *wqh, *wql, *wkh, *wkl, *wvh, *wvl, *woh, *wol;
  cudaGetSymbolAddress((void**)&V, g_V);
  cudaGetSymbolAddress((void**)&ah, g_ah);
  cudaGetSymbolAddress((void**)&al, g_al);
  cudaGetSymbolAddress((void**)&qh, g_qh);
  cudaGetSymbolAddress((void**)&ql, g_ql);
  cudaGetSymbolAddress((void**)&kh, g_kh);
  cudaGetSymbolAddress((void**)&kl, g_kl);
  cudaGetSymbolAddress((void**)&vth, g_vth);
  cudaGetSymbolAddress((void**)&vtl, g_vtl);
  cudaGetSymbolAddress((void**)&wqh, g_wqh);
  cudaGetSymbolAddress((void**)&wql, g_wql);
  cudaGetSymbolAddress((void**)&wkh, g_wkh);
  cudaGetSymbolAddress((void**)&wkl, g_wkl);
  cudaGetSymbolAddress((void**)&wvh, g_wvh);
  cudaGetSymbolAddress((void**)&wvl, g_wvl);
  cudaGetSymbolAddress((void**)&woh, g_woh);
  cudaGetSymbolAddress((void**)&wol, g_wol);

  cudaFuncSetAttribute(gemm_bf16x3,
                       cudaFuncAttributeMaxDynamicSharedMemorySize, GSMEM);
  cudaFuncSetAttribute(attention_mma,
                       cudaFuncAttributeMaxDynamicSharedMemorySize, ASMEM);

  const int NSPLIT = (T_DIM * D_DIM / 4) / 256;
  dim3 gg(D_DIM / BN, T_DIM / BM);
  const float qscale = 0.088388347648318447f;  // 1/sqrt(128)

  split_all<<<dim3(NSPLIT, 1, 5), 256>>>(x, Wq, Wk, Wv, Wo, ah, al, wqh, wql,
                                         wkh, wkl, wvh, wvl, woh, wol);

  gemm_bf16x3<<<gg, 512, GSMEM>>>(ah, al, wqh, wql, bq, nullptr, qh, ql,
                                  qscale, 1);
  gemm_bf16x3<<<gg, 512, GSMEM>>>(ah, al, wkh, wkl, bk, nullptr, kh, kl,
                                  1.f, 1);
  gemm_bf16x3<<<gg, 512, GSMEM>>>(ah, al, wvh, wvl, bv, V, nullptr, nullptr,
                                  1.f, 0);
  transpose_split_v<<<dim3(T_DIM / 32, D_DIM / 32), 256>>>(V, vth, vtl);

  attention_mma<<<dim3(T_DIM / 256, H_NUM), 256, ASMEM>>>(qh, ql, kh, kl, vth,
                                                          vtl, ah, al);

  gemm_bf16x3<<<gg, 512, GSMEM>>>(ah, al, woh, wol, bo, out, nullptr, nullptr,
                                  1.f, 0);
}